// round 8
// baseline (speedup 1.0000x reference)
#include <cuda_runtime.h>
#include <math.h>

#define D 64
#define DTXT 384
typedef unsigned long long ull;

#define MAXE (4 * 1024 * 1024)
#define MAXN 131072

// Scratch (static __device__ per harness rules)
__device__ ull   g_edgesM[MAXE];
__device__ ull   g_edgesA[MAXE];
__device__ float g_bufMA[MAXN * D];
__device__ float g_bufMB[MAXN * D];
__device__ float g_bufAA[MAXN * D];
__device__ float g_bufAB[MAXN * D];
__device__ float g_bufT[2 * MAXN * D];     // normalized text embeddings (M | A)
__device__ int   g_rowptrM[MAXN + 1];
__device__ int   g_rowptrA[MAXN + 1];
__device__ int   g_cnt[2 * MAXN];
__device__ float g_wt[DTXT * D];           // W pre-converted to tf32

// -------------------- W -> tf32 (rna), once --------------------
__global__ void k_prepw(const float* __restrict__ W, float* __restrict__ wt, int n) {
    int i = blockIdx.x * blockDim.x + threadIdx.x;
    if (i < n) {
        unsigned r;
        asm("cvt.rna.tf32.f32 %0, %1;" : "=r"(r) : "f"(W[i]));
        wt[i] = __uint_as_float(r);
    }
}

// -------------------- histogram, 4 edges/thread --------------------
__global__ void k_hist1(const int* __restrict__ rowp, int* __restrict__ cnt, int E) {
    int e0 = (blockIdx.x * blockDim.x + threadIdx.x) * 4;
    if (e0 + 3 < E) {
        int4 r = __ldg((const int4*)(rowp + e0));
        atomicAdd(&cnt[r.x], 1);
        atomicAdd(&cnt[r.y], 1);
        atomicAdd(&cnt[r.z], 1);
        atomicAdd(&cnt[r.w], 1);
    } else {
        for (int k = 0; k < 4; k++)
            if (e0 + k < E) atomicAdd(&cnt[__ldg(rowp + e0 + k)], 1);
    }
}

// -------------------- single-block exclusive scan --------------------
__global__ void k_scan1(int* __restrict__ cnt, int* __restrict__ rowptr, int N) {
    __shared__ int sp[1024];
    int tid = threadIdx.x;
    int chunk = (N + 1023) >> 10;
    int s = tid * chunk;
    int e = min(s + chunk, N);
    int sum = 0;
    for (int i = s; i < e; i++) sum += cnt[i];
    sp[tid] = sum;
    __syncthreads();
    for (int off = 1; off < 1024; off <<= 1) {
        int v = (tid >= off) ? sp[tid - off] : 0;
        __syncthreads();
        sp[tid] += v;
        __syncthreads();
    }
    int excl = (tid == 0) ? 0 : sp[tid - 1];
    for (int i = s; i < e; i++) {
        int c = cnt[i];          // read before overwrite (cnt becomes cursor)
        rowptr[i] = excl;
        cnt[i]    = excl;
        excl += c;
    }
    if (tid == 0) rowptr[N] = sp[1023];
}

// -------------------- scatter, 4 edges/thread --------------------
__global__ void k_scatter1(const int* __restrict__ rowp, const int* __restrict__ colp,
                           const float* __restrict__ valp, int* __restrict__ cur,
                           ull* __restrict__ ed, int E) {
    int e0 = (blockIdx.x * blockDim.x + threadIdx.x) * 4;
    if (e0 + 3 < E) {
        int4   r = __ldg((const int4*)(rowp + e0));
        int4   c = __ldg((const int4*)(colp + e0));
        float4 v = __ldg((const float4*)(valp + e0));
        int p0 = atomicAdd(&cur[r.x], 1);
        int p1 = atomicAdd(&cur[r.y], 1);
        int p2 = atomicAdd(&cur[r.z], 1);
        int p3 = atomicAdd(&cur[r.w], 1);
        ed[p0] = ((ull)__float_as_uint(v.x) << 32) | (unsigned)(c.x * (D * 4));
        ed[p1] = ((ull)__float_as_uint(v.y) << 32) | (unsigned)(c.y * (D * 4));
        ed[p2] = ((ull)__float_as_uint(v.z) << 32) | (unsigned)(c.z * (D * 4));
        ed[p3] = ((ull)__float_as_uint(v.w) << 32) | (unsigned)(c.w * (D * 4));
    } else {
        for (int k = 0; k < 4; k++) {
            int e = e0 + k;
            if (e < E) {
                int r = __ldg(rowp + e);
                int pos = atomicAdd(&cur[r], 1);
                ed[pos] = ((ull)__float_as_uint(__ldg(valp + e)) << 32)
                        | (unsigned)(__ldg(colp + e) * (D * 4));
            }
        }
    }
}

// -------------------- CSR SpMM: half-warp per row, float4 lanes, fused acc --------------------
__global__ void k_spmm_csr(const ull* __restrict__ edges, const int* __restrict__ rowptr,
                           const float* __restrict__ x, const float* __restrict__ accin,
                           float* __restrict__ xnew, float* __restrict__ accout, int N) {
    int tid = blockIdx.x * blockDim.x + threadIdx.x;
    int r = tid >> 4;
    if (r >= N) return;
    int lane16 = threadIdx.x & 15;

    int s = __ldg(rowptr + r);
    int e = __ldg(rowptr + r + 1);

    const char* xb = (const char*)x + lane16 * 16;

    float ax = 0.f, ay = 0.f, az = 0.f, aw = 0.f;
    #pragma unroll 4
    for (int i = s; i < e; i++) {
        ull p = __ldg(edges + i);
        unsigned off = (unsigned)p;
        float v = __uint_as_float((unsigned)(p >> 32));
        float4 xv = __ldg((const float4*)(xb + off));
        ax = fmaf(v, xv.x, ax);
        ay = fmaf(v, xv.y, ay);
        az = fmaf(v, xv.z, az);
        aw = fmaf(v, xv.w, aw);
    }

    float4 base = __ldg((const float4*)(accin + (size_t)r * D) + lane16);
    if (xnew) ((float4*)(xnew + (size_t)r * D))[lane16] = make_float4(ax, ay, az, aw);
    ((float4*)(accout + (size_t)r * D))[lane16] =
        make_float4(base.x + ax, base.y + ay, base.z + az, base.w + aw);
}

#define MMA_TF32(c0,c1,c2,c3,a0,a1,a2,a3,b0,b1)                                     \
    asm volatile("mma.sync.aligned.m16n8k8.row.col.f32.tf32.tf32.f32 "              \
                 "{%0,%1,%2,%3},{%4,%5,%6,%7},{%8,%9},{%0,%1,%2,%3};"               \
                 : "+f"(c0), "+f"(c1), "+f"(c2), "+f"(c3)                           \
                 : "r"(a0), "r"(a1), "r"(a2), "r"(a3), "r"(b0), "r"(b1))

// -------------------- Text GEMM (tf32 HMMA): writes NORMALIZED t to tbuf --------------------
#define ASTR 68
#define BSTR 72
__global__ void k_textgemm(const float* __restrict__ tm, const float* __restrict__ ta,
                           const float* __restrict__ Wt, const float* __restrict__ bias,
                           float* __restrict__ tbuf, int N_M, int N_A) {
    __shared__ float As[64 * ASTR];
    __shared__ float Bs[64 * BSTR];
    __shared__ float s_bias[64];
    __shared__ float s_nt[64];

    const float* T;
    float* tb;
    int N;
    if (blockIdx.y == 0) { T = tm; tb = tbuf;                   N = N_M; }
    else                 { T = ta; tb = tbuf + (size_t)N_M * D; N = N_A; }

    int r0 = blockIdx.x * 64;
    if (r0 >= N) return;

    int tid  = threadIdx.x;
    int wid  = tid >> 5;
    int lane = tid & 31;
    int gid  = lane >> 2;
    int tig  = lane & 3;
    int wr   = (wid >> 1) * 16;
    int wc   = (wid & 1) * 32;

    if (tid < 64) { s_bias[tid] = bias[tid]; s_nt[tid] = 0.f; }

    float c[4][4];
    #pragma unroll
    for (int j = 0; j < 4; j++)
        #pragma unroll
        for (int q = 0; q < 4; q++) c[j][q] = 0.f;

    for (int k0 = 0; k0 < DTXT; k0 += 64) {
        #pragma unroll
        for (int it = 0; it < 4; it++) {
            int fi = tid + it * 256;
            int rr = fi >> 4;
            int kq = fi & 15;
            int gr = r0 + rr;
            float4 v = (gr < N) ? __ldg(((const float4*)(T + (size_t)gr * DTXT + k0)) + kq)
                                : make_float4(0.f, 0.f, 0.f, 0.f);
            *(float4*)(As + rr * ASTR + kq * 4) = v;
        }
        #pragma unroll
        for (int it = 0; it < 4; it++) {
            int fi = tid + it * 256;
            int kk = fi >> 4;
            int cq = fi & 15;
            float4 v = __ldg(((const float4*)(Wt + (size_t)(k0 + kk) * D)) + cq);
            *(float4*)(Bs + kk * BSTR + cq * 4) = v;
        }
        __syncthreads();

        #pragma unroll
        for (int kk = 0; kk < 64; kk += 8) {
            unsigned a0 = __float_as_uint(As[(wr + gid)     * ASTR + kk + tig]);
            unsigned a1 = __float_as_uint(As[(wr + gid + 8) * ASTR + kk + tig]);
            unsigned a2 = __float_as_uint(As[(wr + gid)     * ASTR + kk + tig + 4]);
            unsigned a3 = __float_as_uint(As[(wr + gid + 8) * ASTR + kk + tig + 4]);
            #pragma unroll
            for (int j = 0; j < 4; j++) {
                int cb = wc + j * 8;
                unsigned b0 = __float_as_uint(Bs[(kk + tig)     * BSTR + cb + gid]);
                unsigned b1 = __float_as_uint(Bs[(kk + tig + 4) * BSTR + cb + gid]);
                MMA_TF32(c[j][0], c[j][1], c[j][2], c[j][3], a0, a1, a2, a3, b0, b1);
            }
        }
        __syncthreads();
    }

    int lrA = wr + gid, lrB = lrA + 8;
    int grA = r0 + lrA, grB = r0 + lrB;
    bool okA = grA < N, okB = grB < N;

    float tv[4][4];
    float stA = 0.f, stB = 0.f;
    #pragma unroll
    for (int j = 0; j < 4; j++) {
        int col = wc + j * 8 + 2 * tig;
        float b0 = s_bias[col], b1 = s_bias[col + 1];
        float t0 = c[j][0] + b0, t1 = c[j][1] + b1;
        float t2 = c[j][2] + b0, t3 = c[j][3] + b1;
        tv[j][0] = t0; tv[j][1] = t1; tv[j][2] = t2; tv[j][3] = t3;
        stA += t0 * t0 + t1 * t1;
        stB += t2 * t2 + t3 * t3;
    }
    #pragma unroll
    for (int m = 1; m < 4; m <<= 1) {
        stA += __shfl_xor_sync(0xffffffffu, stA, m);
        stB += __shfl_xor_sync(0xffffffffu, stB, m);
    }
    if (tig == 0) {
        atomicAdd(&s_nt[lrA], stA);
        atomicAdd(&s_nt[lrB], stB);
    }
    __syncthreads();

    float intA = 1.f / fmaxf(sqrtf(s_nt[lrA]), 1e-12f);
    float intB = 1.f / fmaxf(sqrtf(s_nt[lrB]), 1e-12f);

    #pragma unroll
    for (int j = 0; j < 4; j++) {
        int col = wc + j * 8 + 2 * tig;
        if (okA)
            *(float2*)(tb + (size_t)grA * D + col) =
                make_float2(tv[j][0] * intA, tv[j][1] * intA);
        if (okB)
            *(float2*)(tb + (size_t)grB * D + col) =
                make_float2(tv[j][2] * intB, tv[j][3] * intB);
    }
}

// -------------------- Final combine: out = 0.5*(g/||g|| + t_n), half-warp per row --------------------
__global__ void k_final(float* __restrict__ out, const float* __restrict__ tbuf, int Nt) {
    int tid = blockIdx.x * blockDim.x + threadIdx.x;
    int r = tid >> 4;
    if (r >= Nt) return;
    int lane16 = threadIdx.x & 15;

    float4 g = ((const float4*)(out + (size_t)r * D))[lane16];
    float ss = g.x * g.x + g.y * g.y + g.z * g.z + g.w * g.w;
    #pragma unroll
    for (int m = 1; m < 16; m <<= 1)
        ss += __shfl_xor_sync(0xffffffffu, ss, m);
    float inv = 1.f / fmaxf(sqrtf(ss), 1e-12f);

    float4 t = __ldg((const float4*)(tbuf + (size_t)r * D) + lane16);
    ((float4*)(out + (size_t)r * D))[lane16] =
        make_float4(0.5f * (g.x * inv + t.x), 0.5f * (g.y * inv + t.y),
                    0.5f * (g.z * inv + t.z), 0.5f * (g.w * inv + t.w));
}

// -------------------- launch --------------------
extern "C" void kernel_launch(void* const* d_in, const int* in_sizes, int n_in,
                              void* d_out, int out_size) {
    const int*   m_row = (const int*)d_in[0];
    const int*   m_col = (const int*)d_in[1];
    const float* m_val = (const float*)d_in[2];
    const int*   a_row = (const int*)d_in[3];
    const int*   a_col = (const int*)d_in[4];
    const float* a_val = (const float*)d_in[5];
    const float* m_txt = (const float*)d_in[6];
    const float* a_txt = (const float*)d_in[7];
    const float* m_emb = (const float*)d_in[8];
    const float* a_emb = (const float*)d_in[9];
    const float* W     = (const float*)d_in[10];
    const float* bias  = (const float*)d_in[11];

    int E_M = in_sizes[0];
    int E_A = in_sizes[3];
    int N_M = in_sizes[8] / D;
    int N_A = in_sizes[9] / D;

    float* out  = (float*)d_out;
    float* outA = out + (size_t)N_M * D;

    ull*   edM;   cudaGetSymbolAddress((void**)&edM,   g_edgesM);
    ull*   edA;   cudaGetSymbolAddress((void**)&edA,   g_edgesA);
    float* bufMA; cudaGetSymbolAddress((void**)&bufMA, g_bufMA);
    float* bufMB; cudaGetSymbolAddress((void**)&bufMB, g_bufMB);
    float* bufAA; cudaGetSymbolAddress((void**)&bufAA, g_bufAA);
    float* bufAB; cudaGetSymbolAddress((void**)&bufAB, g_bufAB);
    float* bufT;  cudaGetSymbolAddress((void**)&bufT,  g_bufT);
    int*   rpM;   cudaGetSymbolAddress((void**)&rpM,   g_rowptrM);
    int*   rpA;   cudaGetSymbolAddress((void**)&rpA,   g_rowptrA);
    int*   cnt;   cudaGetSymbolAddress((void**)&cnt,   g_cnt);
    float* wt;    cudaGetSymbolAddress((void**)&wt,    g_wt);

    int* cntM = cnt;
    int* cntA = cnt + MAXN;

    const int TB = 256;
    int egM = (E_M + 4 * TB - 1) / (4 * TB);
    int egA = (E_A + 4 * TB - 1) / (4 * TB);
    int sgM = (N_M * 16 + TB - 1) / TB;
    int sgA = (N_A * 16 + TB - 1) / TB;

    cudaStream_t s1, s2;
    cudaStreamCreateWithFlags(&s1, cudaStreamNonBlocking);
    cudaStreamCreateWithFlags(&s2, cudaStreamNonBlocking);
    cudaEvent_t evF, ev1, ev2;
    cudaEventCreateWithFlags(&evF, cudaEventDisableTiming);
    cudaEventCreateWithFlags(&ev1, cudaEventDisableTiming);
    cudaEventCreateWithFlags(&ev2, cudaEventDisableTiming);

    // prep on default stream, then fork
    k_prepw<<<(DTXT * D + TB - 1) / TB, TB>>>(W, wt, DTXT * D);
    cudaMemsetAsync(cnt, 0, 2 * (size_t)MAXN * sizeof(int));
    cudaEventRecord(evF, 0);
    cudaStreamWaitEvent(s1, evF, 0);
    cudaStreamWaitEvent(s2, evF, 0);

    // s0: graph M pipeline
    k_hist1<<<egM, TB>>>(m_row, cntM, E_M);
    k_scan1<<<1, 1024>>>(cntM, rpM, N_M);
    k_scatter1<<<egM, TB>>>(m_row, m_col, m_val, cntM, edM, E_M);
    k_spmm_csr<<<sgM, TB>>>(edM, rpM, m_emb, m_emb, bufMA,     out, N_M);
    k_spmm_csr<<<sgM, TB>>>(edM, rpM, bufMA, out,   bufMB,     out, N_M);
    k_spmm_csr<<<sgM, TB>>>(edM, rpM, bufMB, out,   (float*)0, out, N_M);

    // s1: graph A pipeline
    k_hist1<<<egA, TB, 0, s1>>>(a_row, cntA, E_A);
    k_scan1<<<1, 1024, 0, s1>>>(cntA, rpA, N_A);
    k_scatter1<<<egA, TB, 0, s1>>>(a_row, a_col, a_val, cntA, edA, E_A);
    k_spmm_csr<<<sgA, TB, 0, s1>>>(edA, rpA, a_emb, a_emb, bufAA,     outA, N_A);
    k_spmm_csr<<<sgA, TB, 0, s1>>>(edA, rpA, bufAA, outA,  bufAB,     outA, N_A);
    k_spmm_csr<<<sgA, TB, 0, s1>>>(edA, rpA, bufAB, outA,  (float*)0, outA, N_A);
    cudaEventRecord(ev1, s1);

    // s2: text GEMM (independent of graph output)
    int maxN = (N_M > N_A) ? N_M : N_A;
    dim3 tgrid((maxN + 63) / 64, 2);
    k_textgemm<<<tgrid, 256, 0, s2>>>(m_txt, a_txt, wt, bias, bufT, N_M, N_A);
    cudaEventRecord(ev2, s2);

    // join + final combine on default stream
    cudaStreamWaitEvent(0, ev1, 0);
    cudaStreamWaitEvent(0, ev2, 0);
    int Nt = N_M + N_A;
    k_final<<<(Nt * 16 + TB - 1) / TB, TB>>>(out, bufT, Nt);

    cudaEventDestroy(evF);
    cudaEventDestroy(ev1);
    cudaEventDestroy(ev2);
    cudaStreamDestroy(s1);
    cudaStreamDestroy(s2);
}